// round 14
// baseline (speedup 1.0000x reference)
#include <cuda_runtime.h>
#include <cuda_fp16.h>
#include <cstdint>

#define Bn 8
#define Cn 128
#define Hn 64
#define Wn 64
#define NPIX 32768
#define COUT 128

#define KC    64
#define NCH   18                    // K chunks: 1152/64
#define APLANE ((size_t)NPIX*256)   // bytes per tap plane of A (pix * 128ch * 2B)
#define AROW  144                   // smem row: 128B data + 16B pad
#define ABUF  (256*AROW)            // 36864
#define WBUF  (2*128*AROW)          // 36864 (hi rows 0..127, lo rows 128..255)

// ---- scratch (allocation-free: __device__ globals) ----
__device__ __align__(16) float  g_xt[NPIX*Cn];                  // NHWC x (16 MB)
__device__ __align__(16) float  g_wofft[9*4*Cn];
__device__ __align__(16) float  g_off[NPIX*4];                  // {off0, off1, s1, s2}
__device__ __align__(16) __half g_A[(size_t)9*NPIX*128];        // im2col fp16 (75.5 MB)
__device__ __align__(16) unsigned char g_wimg[NCH*2*128*128];   // W fp16 hi/lo chunk images

// ===========================================================================
// PTX helpers — baseline sm_80 features only
// ===========================================================================
__device__ __forceinline__ uint32_t smem_u32(const void* p) {
    uint32_t a;
    asm("{ .reg .u64 t; cvta.to.shared.u64 t, %1; cvt.u32.u64 %0, t; }" : "=r"(a) : "l"(p));
    return a;
}
__device__ __forceinline__ void cp_async16(uint32_t sdst, const void* gsrc) {
    asm volatile("cp.async.cg.shared.global [%0], [%1], 16;" :: "r"(sdst), "l"(gsrc));
}
#define CP_COMMIT() asm volatile("cp.async.commit_group;")
#define CP_WAIT1()  asm volatile("cp.async.wait_group 1;" ::: "memory")
#define CP_WAIT0()  asm volatile("cp.async.wait_group 0;" ::: "memory")

#define LDSM4(r0,r1,r2,r3,a) \
    asm volatile("ldmatrix.sync.aligned.m8n8.x4.shared.b16 {%0,%1,%2,%3}, [%4];" \
                 : "=r"(r0),"=r"(r1),"=r"(r2),"=r"(r3) : "r"(a))

#define MMAF16(c,a0,a1,a2,a3,b0,b1) \
    asm volatile("mma.sync.aligned.m16n8k16.row.col.f32.f16.f16.f32 " \
                 "{%0,%1,%2,%3}, {%4,%5,%6,%7}, {%8,%9}, {%0,%1,%2,%3};" \
                 : "+f"((c)[0]),"+f"((c)[1]),"+f"((c)[2]),"+f"((c)[3]) \
                 : "r"(a0),"r"(a1),"r"(a2),"r"(a3),"r"(b0),"r"(b1))

// ===========================================================================
// Kernel 1: prep — W -> fp16 hi/lo chunk images for the GEMM; w_off transpose
// g_wimg layout: [chunk][half][n 0..127][64 fp16 = 128B]
// ===========================================================================
__global__ void prep_kernel(const float* __restrict__ w, const float* __restrict__ w_off) {
    int t = blockIdx.x * 256 + threadIdx.x;
    if (t < NCH*128*64) {
        int c = t / (128*64);
        int r = t % (128*64);
        int n = r >> 6;
        int j = r & 63;
        int kg  = c*64 + j;
        int tap = kg >> 7;
        int ch  = kg & 127;
        float v = w[(n*Cn + ch)*9 + tap];
        __half hi = __float2half_rn(v);
        __half lo = __float2half_rn(v - __half2float(hi));
        __half* base = (__half*)(g_wimg + (size_t)c*2*128*128);
        base[(size_t)n*64 + j]            = hi;   // half 0 rows
        base[(size_t)(128 + n)*64 + j]    = lo;   // half 1 rows
    }
    if (t < 9*4*Cn) {
        int tap = t / (4*Cn);
        int r   = t % (4*Cn);
        int oc  = r / Cn;
        int ch  = r % Cn;
        g_wofft[t] = w_off[(oc*Cn + ch)*9 + tap];
    }
}

// ===========================================================================
// Kernel 2: NCHW -> NHWC transpose of x
// ===========================================================================
__global__ void transpose_kernel(const float* __restrict__ x) {
    __shared__ float tile[32][33];
    int bh = blockIdx.z;
    int b = bh >> 6, h = bh & 63;
    int c0 = blockIdx.y * 32;
    int w0 = blockIdx.x * 32;
    int tx = threadIdx.x, ty = threadIdx.y;
    #pragma unroll
    for (int i = 0; i < 32; i += 8)
        tile[ty + i][tx] = x[((b*Cn + c0 + ty + i)*Hn + h)*Wn + w0 + tx];
    __syncthreads();
    #pragma unroll
    for (int i = 0; i < 32; i += 8)
        g_xt[((bh*Wn) + w0 + ty + i)*Cn + c0 + tx] = tile[tx][ty + i];
}

// ===========================================================================
// Kernel 3: offset conv -> per-pixel params {off0, off1, s1, s2}
// ===========================================================================
__global__ __launch_bounds__(256) void offset_kernel(const float* __restrict__ b_off) {
    __shared__ float sw[9*4*Cn];
    int tid = threadIdx.x;
    for (int i = tid; i < 9*4*Cn; i += 256) sw[i] = g_wofft[i];
    __syncthreads();

    int warp = tid >> 5, lane = tid & 31;
    int pix = blockIdx.x * 8 + warp;
    int b   = pix >> 12;
    int rem = pix & 4095;
    int h   = rem >> 6, w = rem & 63;

    float a0 = 0.f, a1 = 0.f, a2 = 0.f, a3 = 0.f;
    const float4* xt4 = (const float4*)g_xt;

    #pragma unroll
    for (int tap = 0; tap < 9; tap++) {
        int dy = tap/3 - 1, dx = tap%3 - 1;
        int yy = h + dy, xx = w + dx;
        if (yy < 0 || yy >= Hn || xx < 0 || xx >= Wn) continue;
        float4 v = xt4[((b*Hn + yy)*Wn + xx)*(Cn/4) + lane];
        const float4* wv = (const float4*)&sw[tap*4*Cn];
        float4 w0v = wv[0*32 + lane];
        float4 w1v = wv[1*32 + lane];
        float4 w2v = wv[2*32 + lane];
        float4 w3v = wv[3*32 + lane];
        a0 += v.x*w0v.x + v.y*w0v.y + v.z*w0v.z + v.w*w0v.w;
        a1 += v.x*w1v.x + v.y*w1v.y + v.z*w1v.z + v.w*w1v.w;
        a2 += v.x*w2v.x + v.y*w2v.y + v.z*w2v.z + v.w*w2v.w;
        a3 += v.x*w3v.x + v.y*w3v.y + v.z*w3v.z + v.w*w3v.w;
    }
    #pragma unroll
    for (int s = 16; s; s >>= 1) {
        a0 += __shfl_xor_sync(0xffffffffu, a0, s);
        a1 += __shfl_xor_sync(0xffffffffu, a1, s);
        a2 += __shfl_xor_sync(0xffffffffu, a2, s);
        a3 += __shfl_xor_sync(0xffffffffu, a3, s);
    }
    if (lane == 0) {
        float4 r;
        r.x = a0 + b_off[0];
        r.y = a1 + b_off[1];
        r.z = fmaxf(a2 + b_off[2], 0.f) + 1.f;
        r.w = fmaxf(a3 + b_off[3], 0.f) + 1.f;
        ((float4*)g_off)[pix] = r;
    }
}

// ===========================================================================
// Kernel 4: sampler (im2col). thread = (pix, 32ch-group); loops 9 taps.
// Writes g_A[tap][pix][128ch] fp16, coalesced. x rows reused from L1 across taps.
// ===========================================================================
__global__ __launch_bounds__(256) void sampler_kernel() {
    int t   = blockIdx.x * 256 + threadIdx.x;   // 0..131071
    int pix = t >> 2;
    int g   = t & 3;
    int b   = pix >> 12;
    int h   = (pix >> 6) & 63;
    int wc  = pix & 63;
    float4 prm = ((const float4*)g_off)[pix];
    const float4* xt4 = (const float4*)g_xt;

    #pragma unroll 1
    for (int tap = 0; tap < 9; tap++) {
        int by = tap/3 - 1, bx = tap - (tap/3)*3 - 1;
        float sk = (by != 0 && bx != 0) ? prm.z : ((by == 0 && bx == 0) ? 0.f : prm.w);
        float py = (float)h  + (float)by * sk + prm.x;
        float px = (float)wc + (float)bx * sk + prm.y;
        float fy = floorf(py), fx = floorf(px);
        float wy = py - fy,    wx = px - fx;
        int y0 = (int)fy, x0 = (int)fx;
        float cw[4] = {(1.f-wy)*(1.f-wx), (1.f-wy)*wx, wy*(1.f-wx), wy*wx};

        float4 samp[8];
        #pragma unroll
        for (int i = 0; i < 8; i++) samp[i] = make_float4(0.f, 0.f, 0.f, 0.f);

        #pragma unroll
        for (int j = 0; j < 4; j++) {
            int yc = y0 + (j >> 1);
            int xc = x0 + (j & 1);
            if (yc < 0 || yc >= Hn || xc < 0 || xc >= Wn) continue;
            const float4* src = xt4 + ((b*Hn + yc)*Wn + xc)*(Cn/4) + g*8;
            float wj = cw[j];
            #pragma unroll
            for (int i = 0; i < 8; i++) {
                float4 v = src[i];
                samp[i].x += wj*v.x; samp[i].y += wj*v.y;
                samp[i].z += wj*v.z; samp[i].w += wj*v.w;
            }
        }
        uint32_t u[16];
        #pragma unroll
        for (int i = 0; i < 8; i++) {
            __half2 p0 = __floats2half2_rn(samp[i].x, samp[i].y);
            __half2 p1 = __floats2half2_rn(samp[i].z, samp[i].w);
            u[i*2]   = *(uint32_t*)&p0;
            u[i*2+1] = *(uint32_t*)&p1;
        }
        char* dst = (char*)g_A + (size_t)tap*APLANE + (size_t)pix*256 + g*64;
        #pragma unroll
        for (int q = 0; q < 4; q++)
            ((uint4*)dst)[q] = make_uint4(u[q*4], u[q*4+1], u[q*4+2], u[q*4+3]);
    }
}

// ===========================================================================
// Kernel 5: streaming fp16 GEMM. 128 blocks (1 wave), block M256 x N128,
// 512 threads, warp tile M64 x N32. K = 1152 in 18 chunks of 64, A and W
// double-buffered via cp.async. Products: a*wh + a*wl (W hi/lo split).
// smem: A0 | A1 | W0 | W1 = 4 x 36864 = 147456 B; epilogue reuses it.
// ===========================================================================
#define SMEM_A0 0
#define SMEM_A1 ABUF
#define SMEM_W0 (2*ABUF)
#define SMEM_W1 (2*ABUF + WBUF)
#define GSMEM   (2*ABUF + 2*WBUF)   // 147456

__device__ __forceinline__ void stage_chunk(uint32_t sb, int c, int pixbase, int tid) {
    uint32_t abuf = sb + ((c & 1) ? SMEM_A1 : SMEM_A0);
    uint32_t wbuf = sb + ((c & 1) ? SMEM_W1 : SMEM_W0);
    const char* Ag = (const char*)g_A + (size_t)(c >> 1)*APLANE + (size_t)(c & 1)*128;
    #pragma unroll
    for (int i = 0; i < 4; i++) {
        int idx = tid + i*512;          // 0..2047
        int r = idx >> 3, seg = idx & 7;
        cp_async16(abuf + r*AROW + seg*16, Ag + (size_t)(pixbase + r)*256 + seg*16);
    }
    const char* Wg = (const char*)g_wimg + (size_t)c*2*128*128;
    #pragma unroll
    for (int i = 0; i < 4; i++) {
        int idx = tid + i*512;
        int r = idx >> 3, seg = idx & 7;  // r: [half][n]
        cp_async16(wbuf + r*AROW + seg*16, Wg + (size_t)r*128 + seg*16);
    }
}

__global__ __launch_bounds__(512, 1) void gemm_kernel(const float* __restrict__ bias,
                                                      float* __restrict__ out) {
    extern __shared__ char smem[];
    uint32_t sb = smem_u32(smem);
    int tid  = threadIdx.x;
    int wid  = tid >> 5;
    int lane = tid & 31;
    int blk  = blockIdx.x;              // 128 blocks
    int b    = blk >> 4;
    int h0   = (blk & 15) << 2;
    int pixbase = blk << 8;

    stage_chunk(sb, 0, pixbase, tid);
    CP_COMMIT();

    int mg = wid & 3;        // M: mg*64
    int ng = wid >> 2;       // N: ng*32
    float acc[4][4][4];
    #pragma unroll
    for (int mi = 0; mi < 4; mi++)
        #pragma unroll
        for (int ni = 0; ni < 4; ni++)
            #pragma unroll
            for (int r = 0; r < 4; r++) acc[mi][ni][r] = 0.f;

    uint32_t a_off[4];
    #pragma unroll
    for (int t16 = 0; t16 < 4; t16++)
        a_off[t16] = (uint32_t)((mg*64 + t16*16 + (lane & 15))*AROW + (lane >> 4)*16);
    uint32_t b_off[2];
    #pragma unroll
    for (int q = 0; q < 2; q++)
        b_off[q] = (uint32_t)((ng*32 + q*16 + ((lane >> 4) & 1)*8 + (lane & 7))*AROW
                              + ((lane >> 3) & 1)*16);

    #pragma unroll 1
    for (int c = 0; c < NCH; c++) {
        if (c < NCH-1) {
            stage_chunk(sb, c+1, pixbase, tid);
            CP_COMMIT();
            CP_WAIT1();
        } else {
            CP_WAIT0();
        }
        __syncthreads();

        uint32_t ab = sb + ((c & 1) ? SMEM_A1 : SMEM_A0);
        uint32_t wb = sb + ((c & 1) ? SMEM_W1 : SMEM_W0);
        #pragma unroll
        for (int kk = 0; kk < 4; kk++) {
            uint32_t ka = (uint32_t)(kk*32);
            uint32_t af[16], bh[8], bl[8];
            #pragma unroll
            for (int t16 = 0; t16 < 4; t16++)
                LDSM4(af[t16*4],af[t16*4+1],af[t16*4+2],af[t16*4+3], ab + a_off[t16] + ka);
            #pragma unroll
            for (int q = 0; q < 2; q++) {
                LDSM4(bh[q*4],bh[q*4+1],bh[q*4+2],bh[q*4+3], wb + b_off[q] + ka);
                LDSM4(bl[q*4],bl[q*4+1],bl[q*4+2],bl[q*4+3], wb + 128*AROW + b_off[q] + ka);
            }
            // product hi: 16 independent acc tiles
            #pragma unroll
            for (int mi = 0; mi < 4; mi++)
                #pragma unroll
                for (int ni = 0; ni < 4; ni++)
                    MMAF16(acc[mi][ni], af[mi*4],af[mi*4+1],af[mi*4+2],af[mi*4+3],
                           bh[ni*2], bh[ni*2+1]);
            // product lo
            #pragma unroll
            for (int mi = 0; mi < 4; mi++)
                #pragma unroll
                for (int ni = 0; ni < 4; ni++)
                    MMAF16(acc[mi][ni], af[mi*4],af[mi*4+1],af[mi*4+2],af[mi*4+3],
                           bl[ni*2], bl[ni*2+1]);
        }
        __syncthreads();
    }

    // ---- epilogue: stage to smem [px][132 floats], then coalesced STG ----
    float* sout = (float*)smem;
    int gq = lane >> 2;
    int tg = lane & 3;
    #pragma unroll
    for (int mi = 0; mi < 4; mi++) {
        int m0 = mg*64 + mi*16 + gq;
        #pragma unroll
        for (int ni = 0; ni < 4; ni++) {
            int o0 = ng*32 + ni*8 + tg*2;
            *(float2*)&sout[m0*132 + o0]     = make_float2(acc[mi][ni][0], acc[mi][ni][1]);
            *(float2*)&sout[(m0+8)*132 + o0] = make_float2(acc[mi][ni][2], acc[mi][ni][3]);
        }
    }
    __syncthreads();

    int o  = tid & 127;
    int hh = tid >> 7;       // 0..3
    float bv = __ldg(&bias[o]);
    float* orow = out + ((size_t)(b*COUT + o)*Hn + h0 + hh)*Wn;
    #pragma unroll
    for (int w4 = 0; w4 < 16; w4++) {
        float4 r;
        r.x = sout[(hh*64 + w4*4 + 0)*132 + o] + bv;
        r.y = sout[(hh*64 + w4*4 + 1)*132 + o] + bv;
        r.z = sout[(hh*64 + w4*4 + 2)*132 + o] + bv;
        r.w = sout[(hh*64 + w4*4 + 3)*132 + o] + bv;
        *(float4*)&orow[w4*4] = r;
    }
}

// ===========================================================================
extern "C" void kernel_launch(void* const* d_in, const int* in_sizes, int n_in,
                              void* d_out, int out_size) {
    const float* x     = (const float*)d_in[0];
    const float* w_off = (const float*)d_in[1];
    const float* b_off = (const float*)d_in[2];
    const float* w     = (const float*)d_in[3];
    const float* bias  = (const float*)d_in[4];
    float* out = (float*)d_out;

    cudaFuncSetAttribute(gemm_kernel, cudaFuncAttributeMaxDynamicSharedMemorySize, GSMEM);

    prep_kernel<<<576, 256>>>(w, w_off);
    transpose_kernel<<<dim3(2, 4, Bn*Hn), dim3(32, 8)>>>(x);
    offset_kernel<<<NPIX/8, 256>>>(b_off);
    sampler_kernel<<<512, 256>>>();
    gemm_kernel<<<128, 512, GSMEM>>>(bias, out);
}

// round 15
// speedup vs baseline: 1.7822x; 1.7822x over previous
#include <cuda_runtime.h>
#include <cuda_fp16.h>
#include <cstdint>

#define Bn 8
#define Cn 128
#define Hn 64
#define Wn 64
#define NPIX 32768
#define COUT 128

#define KC    64
#define NCH   18                    // K chunks: 1152/64
#define APLANE ((size_t)NPIX*256)   // bytes per tap plane of A (pix * 128ch * 2B)
#define AROW  144                   // smem row: 128B data + 16B pad
#define ABUF  (256*AROW)            // 36864
#define WBUF  (2*128*AROW)          // 36864 (hi rows 0..127, lo rows 128..255)

// ---- scratch (allocation-free: __device__ globals) ----
__device__ __align__(16) float  g_xt[NPIX*Cn];                  // NHWC x (16 MB)
__device__ __align__(16) float  g_wofft[9*4*Cn];
__device__ __align__(16) float  g_off[NPIX*4];                  // {off0, off1, s1, s2}
__device__ __align__(16) __half g_A[(size_t)9*NPIX*128];        // im2col fp16 (75.5 MB)
__device__ __align__(16) unsigned char g_wimg[NCH*2*128*128];   // W fp16 hi/lo chunk images

// ===========================================================================
// PTX helpers — baseline sm_80 features only
// ===========================================================================
__device__ __forceinline__ uint32_t smem_u32(const void* p) {
    uint32_t a;
    asm("{ .reg .u64 t; cvta.to.shared.u64 t, %1; cvt.u32.u64 %0, t; }" : "=r"(a) : "l"(p));
    return a;
}
__device__ __forceinline__ void cp_async16(uint32_t sdst, const void* gsrc) {
    asm volatile("cp.async.cg.shared.global [%0], [%1], 16;" :: "r"(sdst), "l"(gsrc));
}
#define CP_COMMIT() asm volatile("cp.async.commit_group;")
#define CP_WAIT1()  asm volatile("cp.async.wait_group 1;" ::: "memory")
#define CP_WAIT0()  asm volatile("cp.async.wait_group 0;" ::: "memory")

#define LDSM4(r0,r1,r2,r3,a) \
    asm volatile("ldmatrix.sync.aligned.m8n8.x4.shared.b16 {%0,%1,%2,%3}, [%4];" \
                 : "=r"(r0),"=r"(r1),"=r"(r2),"=r"(r3) : "r"(a))

#define MMAF16(c,a0,a1,a2,a3,b0,b1) \
    asm volatile("mma.sync.aligned.m16n8k16.row.col.f32.f16.f16.f32 " \
                 "{%0,%1,%2,%3}, {%4,%5,%6,%7}, {%8,%9}, {%0,%1,%2,%3};" \
                 : "+f"((c)[0]),"+f"((c)[1]),"+f"((c)[2]),"+f"((c)[3]) \
                 : "r"(a0),"r"(a1),"r"(a2),"r"(a3),"r"(b0),"r"(b1))

// ===========================================================================
// Kernel 1: prep — W -> fp16 hi/lo chunk images for the GEMM; w_off transpose
// g_wimg layout: [chunk][half][n 0..127][64 fp16 = 128B]
// ===========================================================================
__global__ void prep_kernel(const float* __restrict__ w, const float* __restrict__ w_off) {
    int t = blockIdx.x * 256 + threadIdx.x;
    if (t < NCH*128*64) {
        int c = t / (128*64);
        int r = t % (128*64);
        int n = r >> 6;
        int j = r & 63;
        int kg  = c*64 + j;
        int tap = kg >> 7;
        int ch  = kg & 127;
        float v = w[(n*Cn + ch)*9 + tap];
        __half hi = __float2half_rn(v);
        __half lo = __float2half_rn(v - __half2float(hi));
        __half* base = (__half*)(g_wimg + (size_t)c*2*128*128);
        base[(size_t)n*64 + j]            = hi;   // half 0 rows
        base[(size_t)(128 + n)*64 + j]    = lo;   // half 1 rows
    }
    if (t < 9*4*Cn) {
        int tap = t / (4*Cn);
        int r   = t % (4*Cn);
        int oc  = r / Cn;
        int ch  = r % Cn;
        g_wofft[t] = w_off[(oc*Cn + ch)*9 + tap];
    }
}

// ===========================================================================
// Kernel 2: NCHW -> NHWC transpose of x
// ===========================================================================
__global__ void transpose_kernel(const float* __restrict__ x) {
    __shared__ float tile[32][33];
    int bh = blockIdx.z;
    int b = bh >> 6, h = bh & 63;
    int c0 = blockIdx.y * 32;
    int w0 = blockIdx.x * 32;
    int tx = threadIdx.x, ty = threadIdx.y;
    #pragma unroll
    for (int i = 0; i < 32; i += 8)
        tile[ty + i][tx] = x[((b*Cn + c0 + ty + i)*Hn + h)*Wn + w0 + tx];
    __syncthreads();
    #pragma unroll
    for (int i = 0; i < 32; i += 8)
        g_xt[((bh*Wn) + w0 + ty + i)*Cn + c0 + tx] = tile[tx][ty + i];
}

// ===========================================================================
// Kernel 3: offset conv -> per-pixel params {off0, off1, s1, s2}
// ===========================================================================
__global__ __launch_bounds__(256) void offset_kernel(const float* __restrict__ b_off) {
    __shared__ float sw[9*4*Cn];
    int tid = threadIdx.x;
    for (int i = tid; i < 9*4*Cn; i += 256) sw[i] = g_wofft[i];
    __syncthreads();

    int warp = tid >> 5, lane = tid & 31;
    int pix = blockIdx.x * 8 + warp;
    int b   = pix >> 12;
    int rem = pix & 4095;
    int h   = rem >> 6, w = rem & 63;

    float a0 = 0.f, a1 = 0.f, a2 = 0.f, a3 = 0.f;
    const float4* xt4 = (const float4*)g_xt;

    #pragma unroll
    for (int tap = 0; tap < 9; tap++) {
        int dy = tap/3 - 1, dx = tap%3 - 1;
        int yy = h + dy, xx = w + dx;
        if (yy < 0 || yy >= Hn || xx < 0 || xx >= Wn) continue;
        float4 v = xt4[((b*Hn + yy)*Wn + xx)*(Cn/4) + lane];
        const float4* wv = (const float4*)&sw[tap*4*Cn];
        float4 w0v = wv[0*32 + lane];
        float4 w1v = wv[1*32 + lane];
        float4 w2v = wv[2*32 + lane];
        float4 w3v = wv[3*32 + lane];
        a0 += v.x*w0v.x + v.y*w0v.y + v.z*w0v.z + v.w*w0v.w;
        a1 += v.x*w1v.x + v.y*w1v.y + v.z*w1v.z + v.w*w1v.w;
        a2 += v.x*w2v.x + v.y*w2v.y + v.z*w2v.z + v.w*w2v.w;
        a3 += v.x*w3v.x + v.y*w3v.y + v.z*w3v.z + v.w*w3v.w;
    }
    #pragma unroll
    for (int s = 16; s; s >>= 1) {
        a0 += __shfl_xor_sync(0xffffffffu, a0, s);
        a1 += __shfl_xor_sync(0xffffffffu, a1, s);
        a2 += __shfl_xor_sync(0xffffffffu, a2, s);
        a3 += __shfl_xor_sync(0xffffffffu, a3, s);
    }
    if (lane == 0) {
        float4 r;
        r.x = a0 + b_off[0];
        r.y = a1 + b_off[1];
        r.z = fmaxf(a2 + b_off[2], 0.f) + 1.f;
        r.w = fmaxf(a3 + b_off[3], 0.f) + 1.f;
        ((float4*)g_off)[pix] = r;
    }
}

// ===========================================================================
// Kernel 4: sampler v2 (im2col). One thread = (tap, pix, 16ch-group).
// 2.36M threads. Branchless corners (clamped addr, zeroed weight), loads
// batched in 2 rounds of 8 LDG.128. Warp: g fastest (8 lanes = 128B line).
// ===========================================================================
__global__ __launch_bounds__(256) void sampler_kernel() {
    int t   = blockIdx.x * 256 + threadIdx.x;   // 0 .. 9*NPIX*8-1
    int g   = t & 7;                             // 16-channel group
    int pix = (t >> 3) & (NPIX - 1);
    int tap = t >> 18;                           // NPIX*8 = 262144 = 2^18
    int b   = pix >> 12;
    int h   = (pix >> 6) & 63;
    int wc  = pix & 63;
    float4 prm = ((const float4*)g_off)[pix];

    int by = tap/3 - 1, bx = tap - (tap/3)*3 - 1;
    float sk = (by != 0 && bx != 0) ? prm.z : ((by == 0 && bx == 0) ? 0.f : prm.w);
    float py = (float)h  + (float)by * sk + prm.x;
    float px = (float)wc + (float)bx * sk + prm.y;
    float fy = floorf(py), fx = floorf(px);
    float wy = py - fy,    wx = px - fx;
    int y0 = (int)fy, x0 = (int)fx;
    float cwv[4] = {(1.f-wy)*(1.f-wx), (1.f-wy)*wx, wy*(1.f-wx), wy*wx};

    const float4* srcs[4];
    #pragma unroll
    for (int j = 0; j < 4; j++) {
        int yc = y0 + (j >> 1);
        int xc = x0 + (j & 1);
        bool valid = (yc >= 0 && yc < Hn && xc >= 0 && xc < Wn);
        int yci = min(max(yc, 0), Hn-1);
        int xci = min(max(xc, 0), Wn-1);
        srcs[j] = (const float4*)g_xt + ((b*Hn + yci)*Wn + xci)*(Cn/4) + g*4;
        if (!valid) cwv[j] = 0.f;
    }

    float4 acc[4];
    {   // round 1: corners 0,1 (8 batched loads)
        float4 u[4], v[4];
        #pragma unroll
        for (int i = 0; i < 4; i++) { u[i] = srcs[0][i]; v[i] = srcs[1][i]; }
        #pragma unroll
        for (int i = 0; i < 4; i++) {
            acc[i].x = cwv[0]*u[i].x + cwv[1]*v[i].x;
            acc[i].y = cwv[0]*u[i].y + cwv[1]*v[i].y;
            acc[i].z = cwv[0]*u[i].z + cwv[1]*v[i].z;
            acc[i].w = cwv[0]*u[i].w + cwv[1]*v[i].w;
        }
    }
    {   // round 2: corners 2,3
        float4 u[4], v[4];
        #pragma unroll
        for (int i = 0; i < 4; i++) { u[i] = srcs[2][i]; v[i] = srcs[3][i]; }
        #pragma unroll
        for (int i = 0; i < 4; i++) {
            acc[i].x += cwv[2]*u[i].x + cwv[3]*v[i].x;
            acc[i].y += cwv[2]*u[i].y + cwv[3]*v[i].y;
            acc[i].z += cwv[2]*u[i].z + cwv[3]*v[i].z;
            acc[i].w += cwv[2]*u[i].w + cwv[3]*v[i].w;
        }
    }

    uint32_t u32[8];
    #pragma unroll
    for (int i = 0; i < 4; i++) {
        __half2 p0 = __floats2half2_rn(acc[i].x, acc[i].y);
        __half2 p1 = __floats2half2_rn(acc[i].z, acc[i].w);
        u32[i*2]   = *(uint32_t*)&p0;
        u32[i*2+1] = *(uint32_t*)&p1;
    }
    char* dst = (char*)g_A + (size_t)tap*APLANE + (size_t)pix*256 + g*32;
    ((uint4*)dst)[0] = make_uint4(u32[0], u32[1], u32[2], u32[3]);
    ((uint4*)dst)[1] = make_uint4(u32[4], u32[5], u32[6], u32[7]);
}

// ===========================================================================
// Kernel 5: streaming fp16 GEMM. 128 blocks (1 wave), block M256 x N128,
// 512 threads, warp tile M64 x N32. K = 1152 in 18 chunks of 64, A and W
// double-buffered via cp.async. Products: a*wh + a*wl (W hi/lo split).
// smem: A0 | A1 | W0 | W1 = 4 x 36864 = 147456 B; epilogue reuses it.
// ===========================================================================
#define SMEM_A0 0
#define SMEM_A1 ABUF
#define SMEM_W0 (2*ABUF)
#define SMEM_W1 (2*ABUF + WBUF)
#define GSMEM   (2*ABUF + 2*WBUF)   // 147456

__device__ __forceinline__ void stage_chunk(uint32_t sb, int c, int pixbase, int tid) {
    uint32_t abuf = sb + ((c & 1) ? SMEM_A1 : SMEM_A0);
    uint32_t wbuf = sb + ((c & 1) ? SMEM_W1 : SMEM_W0);
    const char* Ag = (const char*)g_A + (size_t)(c >> 1)*APLANE + (size_t)(c & 1)*128;
    #pragma unroll
    for (int i = 0; i < 4; i++) {
        int idx = tid + i*512;          // 0..2047
        int r = idx >> 3, seg = idx & 7;
        cp_async16(abuf + r*AROW + seg*16, Ag + (size_t)(pixbase + r)*256 + seg*16);
    }
    const char* Wg = (const char*)g_wimg + (size_t)c*2*128*128;
    #pragma unroll
    for (int i = 0; i < 4; i++) {
        int idx = tid + i*512;
        int r = idx >> 3, seg = idx & 7;  // r: [half][n]
        cp_async16(wbuf + r*AROW + seg*16, Wg + (size_t)r*128 + seg*16);
    }
}

__global__ __launch_bounds__(512, 1) void gemm_kernel(const float* __restrict__ bias,
                                                      float* __restrict__ out) {
    extern __shared__ char smem[];
    uint32_t sb = smem_u32(smem);
    int tid  = threadIdx.x;
    int wid  = tid >> 5;
    int lane = tid & 31;
    int blk  = blockIdx.x;              // 128 blocks
    int b    = blk >> 4;
    int h0   = (blk & 15) << 2;
    int pixbase = blk << 8;

    stage_chunk(sb, 0, pixbase, tid);
    CP_COMMIT();

    int mg = wid & 3;        // M: mg*64
    int ng = wid >> 2;       // N: ng*32
    float acc[4][4][4];
    #pragma unroll
    for (int mi = 0; mi < 4; mi++)
        #pragma unroll
        for (int ni = 0; ni < 4; ni++)
            #pragma unroll
            for (int r = 0; r < 4; r++) acc[mi][ni][r] = 0.f;

    uint32_t a_off[4];
    #pragma unroll
    for (int t16 = 0; t16 < 4; t16++)
        a_off[t16] = (uint32_t)((mg*64 + t16*16 + (lane & 15))*AROW + (lane >> 4)*16);
    uint32_t b_off[2];
    #pragma unroll
    for (int q = 0; q < 2; q++)
        b_off[q] = (uint32_t)((ng*32 + q*16 + ((lane >> 4) & 1)*8 + (lane & 7))*AROW
                              + ((lane >> 3) & 1)*16);

    #pragma unroll 1
    for (int c = 0; c < NCH; c++) {
        if (c < NCH-1) {
            stage_chunk(sb, c+1, pixbase, tid);
            CP_COMMIT();
            CP_WAIT1();
        } else {
            CP_WAIT0();
        }
        __syncthreads();

        uint32_t ab = sb + ((c & 1) ? SMEM_A1 : SMEM_A0);
        uint32_t wb = sb + ((c & 1) ? SMEM_W1 : SMEM_W0);
        #pragma unroll
        for (int kk = 0; kk < 4; kk++) {
            uint32_t ka = (uint32_t)(kk*32);
            uint32_t af[16], bh[8], bl[8];
            #pragma unroll
            for (int t16 = 0; t16 < 4; t16++)
                LDSM4(af[t16*4],af[t16*4+1],af[t16*4+2],af[t16*4+3], ab + a_off[t16] + ka);
            #pragma unroll
            for (int q = 0; q < 2; q++) {
                LDSM4(bh[q*4],bh[q*4+1],bh[q*4+2],bh[q*4+3], wb + b_off[q] + ka);
                LDSM4(bl[q*4],bl[q*4+1],bl[q*4+2],bl[q*4+3], wb + 128*AROW + b_off[q] + ka);
            }
            // product hi: 16 independent acc tiles
            #pragma unroll
            for (int mi = 0; mi < 4; mi++)
                #pragma unroll
                for (int ni = 0; ni < 4; ni++)
                    MMAF16(acc[mi][ni], af[mi*4],af[mi*4+1],af[mi*4+2],af[mi*4+3],
                           bh[ni*2], bh[ni*2+1]);
            // product lo
            #pragma unroll
            for (int mi = 0; mi < 4; mi++)
                #pragma unroll
                for (int ni = 0; ni < 4; ni++)
                    MMAF16(acc[mi][ni], af[mi*4],af[mi*4+1],af[mi*4+2],af[mi*4+3],
                           bl[ni*2], bl[ni*2+1]);
        }
        __syncthreads();
    }

    // ---- epilogue: stage to smem [px][132 floats], then coalesced STG ----
    float* sout = (float*)smem;
    int gq = lane >> 2;
    int tg = lane & 3;
    #pragma unroll
    for (int mi = 0; mi < 4; mi++) {
        int m0 = mg*64 + mi*16 + gq;
        #pragma unroll
        for (int ni = 0; ni < 4; ni++) {
            int o0 = ng*32 + ni*8 + tg*2;
            *(float2*)&sout[m0*132 + o0]     = make_float2(acc[mi][ni][0], acc[mi][ni][1]);
            *(float2*)&sout[(m0+8)*132 + o0] = make_float2(acc[mi][ni][2], acc[mi][ni][3]);
        }
    }
    __syncthreads();

    int o  = tid & 127;
    int hh = tid >> 7;       // 0..3
    float bv = __ldg(&bias[o]);
    float* orow = out + ((size_t)(b*COUT + o)*Hn + h0 + hh)*Wn;
    #pragma unroll
    for (int w4 = 0; w4 < 16; w4++) {
        float4 r;
        r.x = sout[(hh*64 + w4*4 + 0)*132 + o] + bv;
        r.y = sout[(hh*64 + w4*4 + 1)*132 + o] + bv;
        r.z = sout[(hh*64 + w4*4 + 2)*132 + o] + bv;
        r.w = sout[(hh*64 + w4*4 + 3)*132 + o] + bv;
        *(float4*)&orow[w4*4] = r;
    }
}

// ===========================================================================
extern "C" void kernel_launch(void* const* d_in, const int* in_sizes, int n_in,
                              void* d_out, int out_size) {
    const float* x     = (const float*)d_in[0];
    const float* w_off = (const float*)d_in[1];
    const float* b_off = (const float*)d_in[2];
    const float* w     = (const float*)d_in[3];
    const float* bias  = (const float*)d_in[4];
    float* out = (float*)d_out;

    cudaFuncSetAttribute(gemm_kernel, cudaFuncAttributeMaxDynamicSharedMemorySize, GSMEM);

    prep_kernel<<<576, 256>>>(w, w_off);
    transpose_kernel<<<dim3(2, 4, Bn*Hn), dim3(32, 8)>>>(x);
    offset_kernel<<<NPIX/8, 256>>>(b_off);
    sampler_kernel<<<9*NPIX*8/256, 256>>>();
    gemm_kernel<<<128, 512, GSMEM>>>(bias, out);
}

// round 16
// speedup vs baseline: 2.7258x; 1.5295x over previous
#include <cuda_runtime.h>
#include <cuda_fp16.h>
#include <cstdint>

#define Bn 8
#define Cn 128
#define Hn 64
#define Wn 64
#define NPIX 32768
#define COUT 128

#define NCH   18                    // K chunks: 1152/64
#define APLANE ((size_t)NPIX*256)   // bytes per tap plane of A (pix * 128ch * 2B)
#define AROW  144                   // smem row: 128B data + 16B pad
#define ABUF  (256*AROW)            // 36864
#define WBUF  (128*AROW)            // 18432 (hi only)

// ---- scratch (allocation-free: __device__ globals) ----
__device__ __align__(16) float  g_xt[NPIX*Cn];                  // NHWC x fp32 (16 MB, offset conv)
__device__ __align__(16) __half g_xh[NPIX*Cn];                  // NHWC x fp16 (8 MB, sampler)
__device__ __align__(16) float  g_wofft[9*4*Cn];
__device__ __align__(16) float  g_off[NPIX*4];                  // {off0, off1, s1, s2}
__device__ __align__(16) __half g_A[(size_t)9*NPIX*128];        // im2col fp16 (75.5 MB)
__device__ __align__(16) unsigned char g_wimg[NCH*128*128];     // W fp16 chunk images (hi only)

// ===========================================================================
// PTX helpers — baseline sm_80 features only
// ===========================================================================
__device__ __forceinline__ uint32_t smem_u32(const void* p) {
    uint32_t a;
    asm("{ .reg .u64 t; cvta.to.shared.u64 t, %1; cvt.u32.u64 %0, t; }" : "=r"(a) : "l"(p));
    return a;
}
__device__ __forceinline__ void cp_async16(uint32_t sdst, const void* gsrc) {
    asm volatile("cp.async.cg.shared.global [%0], [%1], 16;" :: "r"(sdst), "l"(gsrc));
}
#define CP_COMMIT() asm volatile("cp.async.commit_group;")
#define CP_WAIT1()  asm volatile("cp.async.wait_group 1;" ::: "memory")
#define CP_WAIT0()  asm volatile("cp.async.wait_group 0;" ::: "memory")

#define LDSM4(r0,r1,r2,r3,a) \
    asm volatile("ldmatrix.sync.aligned.m8n8.x4.shared.b16 {%0,%1,%2,%3}, [%4];" \
                 : "=r"(r0),"=r"(r1),"=r"(r2),"=r"(r3) : "r"(a))

#define MMAF16(c,a0,a1,a2,a3,b0,b1) \
    asm volatile("mma.sync.aligned.m16n8k16.row.col.f32.f16.f16.f32 " \
                 "{%0,%1,%2,%3}, {%4,%5,%6,%7}, {%8,%9}, {%0,%1,%2,%3};" \
                 : "+f"((c)[0]),"+f"((c)[1]),"+f"((c)[2]),"+f"((c)[3]) \
                 : "r"(a0),"r"(a1),"r"(a2),"r"(a3),"r"(b0),"r"(b1))

// ===========================================================================
// Kernel 1: prep — W -> fp16 chunk images [chunk][n][64 fp16]; w_off transpose
// ===========================================================================
__global__ void prep_kernel(const float* __restrict__ w, const float* __restrict__ w_off) {
    int t = blockIdx.x * 256 + threadIdx.x;
    if (t < NCH*128*64) {
        int c = t / (128*64);
        int r = t % (128*64);
        int n = r >> 6;
        int j = r & 63;
        int kg  = c*64 + j;
        int tap = kg >> 7;
        int ch  = kg & 127;
        float v = w[(n*Cn + ch)*9 + tap];
        ((__half*)(g_wimg + (size_t)c*128*128))[(size_t)n*64 + j] = __float2half_rn(v);
    }
    if (t < 9*4*Cn) {
        int tap = t / (4*Cn);
        int r   = t % (4*Cn);
        int oc  = r / Cn;
        int ch  = r % Cn;
        g_wofft[t] = w_off[(oc*Cn + ch)*9 + tap];
    }
}

// ===========================================================================
// Kernel 2: NCHW -> NHWC transpose of x (writes fp32 and fp16 copies)
// ===========================================================================
__global__ void transpose_kernel(const float* __restrict__ x) {
    __shared__ float tile[32][33];
    int bh = blockIdx.z;
    int b = bh >> 6, h = bh & 63;
    int c0 = blockIdx.y * 32;
    int w0 = blockIdx.x * 32;
    int tx = threadIdx.x, ty = threadIdx.y;
    #pragma unroll
    for (int i = 0; i < 32; i += 8)
        tile[ty + i][tx] = x[((b*Cn + c0 + ty + i)*Hn + h)*Wn + w0 + tx];
    __syncthreads();
    #pragma unroll
    for (int i = 0; i < 32; i += 8) {
        float v = tile[tx][ty + i];
        size_t idx = (size_t)((bh*Wn) + w0 + ty + i)*Cn + c0 + tx;
        g_xt[idx] = v;
        g_xh[idx] = __float2half_rn(v);
    }
}

// ===========================================================================
// Kernel 3: offset conv -> per-pixel params {off0, off1, s1, s2} (fp32 exact)
// ===========================================================================
__global__ __launch_bounds__(256) void offset_kernel(const float* __restrict__ b_off) {
    __shared__ float sw[9*4*Cn];
    int tid = threadIdx.x;
    for (int i = tid; i < 9*4*Cn; i += 256) sw[i] = g_wofft[i];
    __syncthreads();

    int warp = tid >> 5, lane = tid & 31;
    int pix = blockIdx.x * 8 + warp;
    int b   = pix >> 12;
    int rem = pix & 4095;
    int h   = rem >> 6, w = rem & 63;

    float a0 = 0.f, a1 = 0.f, a2 = 0.f, a3 = 0.f;
    const float4* xt4 = (const float4*)g_xt;

    #pragma unroll
    for (int tap = 0; tap < 9; tap++) {
        int dy = tap/3 - 1, dx = tap%3 - 1;
        int yy = h + dy, xx = w + dx;
        if (yy < 0 || yy >= Hn || xx < 0 || xx >= Wn) continue;
        float4 v = xt4[((b*Hn + yy)*Wn + xx)*(Cn/4) + lane];
        const float4* wv = (const float4*)&sw[tap*4*Cn];
        float4 w0v = wv[0*32 + lane];
        float4 w1v = wv[1*32 + lane];
        float4 w2v = wv[2*32 + lane];
        float4 w3v = wv[3*32 + lane];
        a0 += v.x*w0v.x + v.y*w0v.y + v.z*w0v.z + v.w*w0v.w;
        a1 += v.x*w1v.x + v.y*w1v.y + v.z*w1v.z + v.w*w1v.w;
        a2 += v.x*w2v.x + v.y*w2v.y + v.z*w2v.z + v.w*w2v.w;
        a3 += v.x*w3v.x + v.y*w3v.y + v.z*w3v.z + v.w*w3v.w;
    }
    #pragma unroll
    for (int s = 16; s; s >>= 1) {
        a0 += __shfl_xor_sync(0xffffffffu, a0, s);
        a1 += __shfl_xor_sync(0xffffffffu, a1, s);
        a2 += __shfl_xor_sync(0xffffffffu, a2, s);
        a3 += __shfl_xor_sync(0xffffffffu, a3, s);
    }
    if (lane == 0) {
        float4 r;
        r.x = a0 + b_off[0];
        r.y = a1 + b_off[1];
        r.z = fmaxf(a2 + b_off[2], 0.f) + 1.f;
        r.w = fmaxf(a3 + b_off[3], 0.f) + 1.f;
        ((float4*)g_off)[pix] = r;
    }
}

// ===========================================================================
// Kernel 4: sampler v3 (im2col from fp16 x). One thread = (tap, pix, 8ch-group).
// 4.7M threads; per thread: 4 batched LDG.128 (one per corner), fp32 math,
// one 16B store. Warp: 16 lanes cover a 256B pixel row contiguously.
// ===========================================================================
__global__ __launch_bounds__(256) void sampler_kernel() {
    int t   = blockIdx.x * 256 + threadIdx.x;   // 0 .. 9*NPIX*16-1
    int g   = t & 15;                            // 8-channel group
    int pix = (t >> 4) & (NPIX - 1);
    int tap = t >> 19;                           // NPIX*16 = 2^19
    int b   = pix >> 12;
    int h   = (pix >> 6) & 63;
    int wc  = pix & 63;
    float4 prm = ((const float4*)g_off)[pix];

    int by = tap/3 - 1, bx = tap - (tap/3)*3 - 1;
    float sk = (by != 0 && bx != 0) ? prm.z : ((by == 0 && bx == 0) ? 0.f : prm.w);
    float py = (float)h  + (float)by * sk + prm.x;
    float px = (float)wc + (float)bx * sk + prm.y;
    float fy = floorf(py), fx = floorf(px);
    float wy = py - fy,    wx = px - fx;
    int y0 = (int)fy, x0 = (int)fx;
    float cwv[4] = {(1.f-wy)*(1.f-wx), (1.f-wy)*wx, wy*(1.f-wx), wy*wx};

    const uint4* srcs[4];
    #pragma unroll
    for (int j = 0; j < 4; j++) {
        int yc = y0 + (j >> 1);
        int xc = x0 + (j & 1);
        bool valid = (yc >= 0 && yc < Hn && xc >= 0 && xc < Wn);
        int yci = min(max(yc, 0), Hn-1);
        int xci = min(max(xc, 0), Wn-1);
        srcs[j] = (const uint4*)g_xh + ((b*Hn + yci)*Wn + xci)*16 + g;   // row = 16 uint4
        if (!valid) cwv[j] = 0.f;
    }

    uint4 d0 = *srcs[0], d1 = *srcs[1], d2 = *srcs[2], d3 = *srcs[3];   // MLP 4

    float accf[8];
    {
        const __half2* h0 = (const __half2*)&d0;
        const __half2* h1 = (const __half2*)&d1;
        const __half2* h2 = (const __half2*)&d2;
        const __half2* h3 = (const __half2*)&d3;
        #pragma unroll
        for (int q = 0; q < 4; q++) {
            float2 f0 = __half22float2(h0[q]);
            float2 f1 = __half22float2(h1[q]);
            float2 f2 = __half22float2(h2[q]);
            float2 f3 = __half22float2(h3[q]);
            accf[q*2]   = cwv[0]*f0.x + cwv[1]*f1.x + cwv[2]*f2.x + cwv[3]*f3.x;
            accf[q*2+1] = cwv[0]*f0.y + cwv[1]*f1.y + cwv[2]*f2.y + cwv[3]*f3.y;
        }
    }

    uint32_t u32[4];
    #pragma unroll
    for (int q = 0; q < 4; q++) {
        __half2 p = __floats2half2_rn(accf[q*2], accf[q*2+1]);
        u32[q] = *(uint32_t*)&p;
    }
    char* dst = (char*)g_A + (size_t)tap*APLANE + (size_t)pix*256 + g*16;
    *(uint4*)dst = make_uint4(u32[0], u32[1], u32[2], u32[3]);
}

// ===========================================================================
// Kernel 5: streaming fp16 GEMM (single product, W hi only).
// 128 blocks (1 wave), block M256 x N128, 512 threads, warp tile M64 x N32.
// K = 1152 in 18 chunks of 64; A and W double-buffered via cp.async.
// smem: A0 | A1 | W0 | W1 = 110592 B; epilogue needs 135168 -> GSMEM 135168.
// ===========================================================================
#define SMEM_A0 0
#define SMEM_A1 ABUF
#define SMEM_W0 (2*ABUF)
#define SMEM_W1 (2*ABUF + WBUF)
#define GSMEM   135168

__device__ __forceinline__ void stage_chunk(uint32_t sb, int c, int pixbase, int tid) {
    uint32_t abuf = sb + ((c & 1) ? SMEM_A1 : SMEM_A0);
    uint32_t wbuf = sb + ((c & 1) ? SMEM_W1 : SMEM_W0);
    const char* Ag = (const char*)g_A + (size_t)(c >> 1)*APLANE + (size_t)(c & 1)*128;
    #pragma unroll
    for (int i = 0; i < 4; i++) {
        int idx = tid + i*512;          // 0..2047
        int r = idx >> 3, seg = idx & 7;
        cp_async16(abuf + r*AROW + seg*16, Ag + (size_t)(pixbase + r)*256 + seg*16);
    }
    const char* Wg = (const char*)g_wimg + (size_t)c*128*128;
    #pragma unroll
    for (int i = 0; i < 2; i++) {
        int idx = tid + i*512;          // 0..1023
        int r = idx >> 3, seg = idx & 7;
        cp_async16(wbuf + r*AROW + seg*16, Wg + (size_t)r*128 + seg*16);
    }
}

__global__ __launch_bounds__(512, 1) void gemm_kernel(const float* __restrict__ bias,
                                                      float* __restrict__ out) {
    extern __shared__ char smem[];
    uint32_t sb = smem_u32(smem);
    int tid  = threadIdx.x;
    int wid  = tid >> 5;
    int lane = tid & 31;
    int blk  = blockIdx.x;              // 128 blocks
    int b    = blk >> 4;
    int h0   = (blk & 15) << 2;
    int pixbase = blk << 8;

    stage_chunk(sb, 0, pixbase, tid);
    CP_COMMIT();

    int mg = wid & 3;        // M: mg*64
    int ng = wid >> 2;       // N: ng*32
    float acc[4][4][4];
    #pragma unroll
    for (int mi = 0; mi < 4; mi++)
        #pragma unroll
        for (int ni = 0; ni < 4; ni++)
            #pragma unroll
            for (int r = 0; r < 4; r++) acc[mi][ni][r] = 0.f;

    uint32_t a_off[4];
    #pragma unroll
    for (int t16 = 0; t16 < 4; t16++)
        a_off[t16] = (uint32_t)((mg*64 + t16*16 + (lane & 15))*AROW + (lane >> 4)*16);
    uint32_t b_off[2];
    #pragma unroll
    for (int q = 0; q < 2; q++)
        b_off[q] = (uint32_t)((ng*32 + q*16 + ((lane >> 4) & 1)*8 + (lane & 7))*AROW
                              + ((lane >> 3) & 1)*16);

    #pragma unroll 1
    for (int c = 0; c < NCH; c++) {
        if (c < NCH-1) {
            stage_chunk(sb, c+1, pixbase, tid);
            CP_COMMIT();
            CP_WAIT1();
        } else {
            CP_WAIT0();
        }
        __syncthreads();

        uint32_t ab = sb + ((c & 1) ? SMEM_A1 : SMEM_A0);
        uint32_t wb = sb + ((c & 1) ? SMEM_W1 : SMEM_W0);
        #pragma unroll
        for (int kk = 0; kk < 4; kk++) {
            uint32_t ka = (uint32_t)(kk*32);
            uint32_t af[16], bh[8];
            #pragma unroll
            for (int t16 = 0; t16 < 4; t16++)
                LDSM4(af[t16*4],af[t16*4+1],af[t16*4+2],af[t16*4+3], ab + a_off[t16] + ka);
            #pragma unroll
            for (int q = 0; q < 2; q++)
                LDSM4(bh[q*4],bh[q*4+1],bh[q*4+2],bh[q*4+3], wb + b_off[q] + ka);
            #pragma unroll
            for (int mi = 0; mi < 4; mi++)
                #pragma unroll
                for (int ni = 0; ni < 4; ni++)
                    MMAF16(acc[mi][ni], af[mi*4],af[mi*4+1],af[mi*4+2],af[mi*4+3],
                           bh[ni*2], bh[ni*2+1]);
        }
        __syncthreads();
    }

    // ---- epilogue: stage to smem [px][132 floats], then coalesced STG ----
    float* sout = (float*)smem;
    int gq = lane >> 2;
    int tg = lane & 3;
    #pragma unroll
    for (int mi = 0; mi < 4; mi++) {
        int m0 = mg*64 + mi*16 + gq;
        #pragma unroll
        for (int ni = 0; ni < 4; ni++) {
            int o0 = ng*32 + ni*8 + tg*2;
            *(float2*)&sout[m0*132 + o0]     = make_float2(acc[mi][ni][0], acc[mi][ni][1]);
            *(float2*)&sout[(m0+8)*132 + o0] = make_float2(acc[mi][ni][2], acc[mi][ni][3]);
        }
    }
    __syncthreads();

    int o  = tid & 127;
    int hh = tid >> 7;       // 0..3
    float bv = __ldg(&bias[o]);
    float* orow = out + ((size_t)(b*COUT + o)*Hn + h0 + hh)*Wn;
    #pragma unroll
    for (int w4 = 0; w4 < 16; w4++) {
        float4 r;
        r.x = sout[(hh*64 + w4*4 + 0)*132 + o] + bv;
        r.y = sout[(hh*64 + w4*4 + 1)*132 + o] + bv;
        r.z = sout[(hh*64 + w4*4 + 2)*132 + o] + bv;
        r.w = sout[(hh*64 + w4*4 + 3)*132 + o] + bv;
        *(float4*)&orow[w4*4] = r;
    }
}

// ===========================================================================
extern "C" void kernel_launch(void* const* d_in, const int* in_sizes, int n_in,
                              void* d_out, int out_size) {
    const float* x     = (const float*)d_in[0];
    const float* w_off = (const float*)d_in[1];
    const float* b_off = (const float*)d_in[2];
    const float* w     = (const float*)d_in[3];
    const float* bias  = (const float*)d_in[4];
    float* out = (float*)d_out;

    cudaFuncSetAttribute(gemm_kernel, cudaFuncAttributeMaxDynamicSharedMemorySize, GSMEM);

    prep_kernel<<<576, 256>>>(w, w_off);
    transpose_kernel<<<dim3(2, 4, Bn*Hn), dim3(32, 8)>>>(x);
    offset_kernel<<<NPIX/8, 256>>>(b_off);
    sampler_kernel<<<9*NPIX*16/256, 256>>>();
    gemm_kernel<<<128, 512, GSMEM>>>(bias, out);
}